// round 12
// baseline (speedup 1.0000x reference)
#include <cuda_runtime.h>

#define NBT 16320  // 64 * 255

// compact exp blocks: g_expT[bt*512 + k*64 + c*8 + r] = E_k[r][c], bt = b*255+t
__device__ float g_expT[NBT * 512];

static __device__ __forceinline__ unsigned long long pk2(float lo, float hi) {
    unsigned long long r;
    asm("mov.b64 %0, {%1,%2};" : "=l"(r) : "f"(lo), "f"(hi));
    return r;
}
static __device__ __forceinline__ void upk2(unsigned long long v, float& lo, float& hi) {
    asm("mov.b64 {%0,%1}, %2;" : "=f"(lo), "=f"(hi) : "l"(v));
}
static __device__ __forceinline__ unsigned long long fma2_(unsigned long long a,
                                                           unsigned long long b,
                                                           unsigned long long c) {
    unsigned long long d;
    asm("fma.rn.f32x2 %0, %1, %2, %3;" : "=l"(d) : "l"(a), "l"(b), "l"(c));
    return d;
}

// Shared-memory union for the merged enc+phi kernel.
union EncPhiSmem {
    struct {
        float actS[2][32];
        float Ablk[16 * 68];
        float Esm[16 * 72];
    } phi;
    struct {
        float obsS[64 * 68];
        float Wsm[64 * 64];
    } enc;
};

// ---------------- encoder body: latent = obs @ We + be ---------------------
// 64x64 tile, 256 thr, thread = 4 rows x 4 cols. Register double-buffered
// K chunks of 64. W natural layout: cols tx*4 contiguous -> conflict-free.
static __device__ __forceinline__ void enc_body(EncPhiSmem* sm, int blk,
                                                const float* __restrict__ obs,
                                                const float* __restrict__ We,
                                                const float* __restrict__ be,
                                                float* __restrict__ latent) {
    float* obsS = sm->enc.obsS;
    float* Wsm = sm->enc.Wsm;
    const int tid = threadIdx.x;
    const int tx = tid & 15, ty = tid >> 4;   // tx: col group (4), ty: 0..15
    const int row0 = blk * 64;
    const int cb = tx * 4;

    unsigned long long acc[4][2];
    {
        unsigned long long b0 = pk2(be[cb + 0], be[cb + 1]);
        unsigned long long b1 = pk2(be[cb + 2], be[cb + 3]);
#pragma unroll
        for (int r = 0; r < 4; r++) { acc[r][0] = b0; acc[r][1] = b1; }
    }

    float4 rA[4], rW[4];
#pragma unroll
    for (int n = 0; n < 4; n++) {
        int i = tid + n * 256;
        int rr = i >> 4, c4 = (i & 15) * 4;
        rA[n] = *(const float4*)&obs[(size_t)(row0 + rr) * 512 + c4];
        rW[n] = *(const float4*)&We[(size_t)rr * 64 + c4];
    }
    for (int kc = 0; kc < 8; kc++) {
#pragma unroll
        for (int n = 0; n < 4; n++) {
            int i = tid + n * 256;
            int rr = i >> 4, c4 = (i & 15) * 4;
            *(float4*)&obsS[rr * 68 + c4] = rA[n];
            *(float4*)&Wsm[rr * 64 + c4] = rW[n];
        }
        __syncthreads();
        if (kc < 7) {
#pragma unroll
            for (int n = 0; n < 4; n++) {
                int i = tid + n * 256;
                int rr = i >> 4, c4 = (i & 15) * 4;
                rA[n] = *(const float4*)&obs[(size_t)(row0 + rr) * 512 + (kc + 1) * 64 + c4];
                rW[n] = *(const float4*)&We[(size_t)((kc + 1) * 64 + rr) * 64 + c4];
            }
        }
#pragma unroll
        for (int k4 = 0; k4 < 16; k4++) {
            float4 o4[4];
#pragma unroll
            for (int r = 0; r < 4; r++)
                o4[r] = *(const float4*)&obsS[(ty + r * 16) * 68 + k4 * 4];
#pragma unroll
            for (int kk = 0; kk < 4; kk++) {
                int k = k4 * 4 + kk;
                ulonglong2 w = *(const ulonglong2*)&Wsm[k * 64 + tx * 4];
#pragma unroll
                for (int r = 0; r < 4; r++) {
                    float o = (kk == 0) ? o4[r].x : (kk == 1) ? o4[r].y
                              : (kk == 2) ? o4[r].z : o4[r].w;
                    unsigned long long o2 = pk2(o, o);
                    acc[r][0] = fma2_(o2, w.x, acc[r][0]);
                    acc[r][1] = fma2_(o2, w.y, acc[r][1]);
                }
            }
        }
        __syncthreads();
    }
#pragma unroll
    for (int r = 0; r < 4; r++) {
        float v0, v1, v2, v3;
        upk2(acc[r][0], v0, v1); upk2(acc[r][1], v2, v3);
        *(float4*)&latent[(size_t)(row0 + ty + r * 16) * 64 + cb] =
            make_float4(v0, v1, v2, v3);
    }
}

// ---------------- phi body: phi GEMM + expm + rho --------------------------
// 2 (b,t) pairs per block = 16 8x8 matrices. expm uses 16 lanes/matrix:
// lane owns HALF a column (4 rows) -> per-lane A = 32 floats = 32 regs.
static __device__ __forceinline__ void phi_body(EncPhiSmem* sm, int blk,
                                                const float* __restrict__ act,
                                                const float* __restrict__ Wp,
                                                const float* __restrict__ bp,
                                                float* __restrict__ rho) {
    float (*actS)[32] = sm->phi.actS;
    float* Ablk = sm->phi.Ablk;
    float* Esm = sm->phi.Esm;
    const int tid = threadIdx.x;
    const int bt0 = blk * 2;

    for (int i = tid; i < 64; i += 256)
        actS[i >> 5][i & 31] = act[(size_t)bt0 * 32 + i];
    __syncthreads();

    // after_phi = act @ Wp + bp for 2 bt's; Wp loaded in-loop (low regs)
    {
        const int j0 = tid * 2;
        const unsigned long long bb2 = *(const unsigned long long*)&bp[j0];
        unsigned long long s0 = bb2, s1 = bb2;
#pragma unroll 8
        for (int a = 0; a < 32; a++) {
            unsigned long long w = *(const unsigned long long*)&Wp[a * 512 + j0];
            float f0 = actS[0][a], f1 = actS[1][a];
            s0 = fma2_(pk2(f0, f0), w, s0);
            s1 = fma2_(pk2(f1, f1), w, s1);
        }
        const int k = j0 >> 6, rowj = (j0 >> 3) & 7, colj = j0 & 7;
        float v0, v1;
        upk2(s0, v0, v1);
        Ablk[(0 * 8 + k) * 68 + colj * 8 + rowj] = v0;
        Ablk[(0 * 8 + k) * 68 + (colj + 1) * 8 + rowj] = v1;
        upk2(s1, v0, v1);
        Ablk[(1 * 8 + k) * 68 + colj * 8 + rowj] = v0;
        Ablk[(1 * 8 + k) * 68 + (colj + 1) * 8 + rowj] = v1;
    }
    __syncthreads();

    // expm: 16 lanes per matrix m. lane l = tid&15: lc = l&7 (column),
    // hs = l>>3 (row half). exp(A) = (Taylor10(A/4))^4.
    const int m = tid >> 4;
    const int l = tid & 15, lc = l & 7, hs = l >> 3;
    const int rb = hs * 4;
    const float* Am = &Ablk[m * 68];

    // A2[kk][p] = ( As[rb+2p][kk], As[rb+2p+1][kk] ), As = A*0.25
    unsigned long long A2[8][2];
#pragma unroll
    for (int p = 0; p < 2; p++) {
        float4 a0 = *(const float4*)&Am[(rb + 2 * p) * 8];
        float4 a1 = *(const float4*)&Am[(rb + 2 * p) * 8 + 4];
        float4 b0 = *(const float4*)&Am[(rb + 2 * p + 1) * 8];
        float4 b1 = *(const float4*)&Am[(rb + 2 * p + 1) * 8 + 4];
        A2[0][p] = pk2(a0.x * 0.25f, b0.x * 0.25f);
        A2[1][p] = pk2(a0.y * 0.25f, b0.y * 0.25f);
        A2[2][p] = pk2(a0.z * 0.25f, b0.z * 0.25f);
        A2[3][p] = pk2(a0.w * 0.25f, b0.w * 0.25f);
        A2[4][p] = pk2(a1.x * 0.25f, b1.x * 0.25f);
        A2[5][p] = pk2(a1.y * 0.25f, b1.y * 0.25f);
        A2[6][p] = pk2(a1.z * 0.25f, b1.z * 0.25f);
        A2[7][p] = pk2(a1.w * 0.25f, b1.w * 0.25f);
    }
    unsigned long long idv2[2];
#pragma unroll
    for (int p = 0; p < 2; p++)
        idv2[p] = pk2(lc == rb + 2 * p ? 1.0f : 0.0f,
                      lc == rb + 2 * p + 1 ? 1.0f : 0.0f);
    // init R = I + As/10  (column lc, my half rows)
    unsigned long long Rc2[2];
#pragma unroll
    for (int p = 0; p < 2; p++) {
        float a0 = Am[(rb + 2 * p) * 8 + lc] * 0.025f;
        float a1 = Am[(rb + 2 * p + 1) * 8 + lc] * 0.025f;
        Rc2[p] = pk2(a0 + (lc == rb + 2 * p ? 1.0f : 0.0f),
                     a1 + (lc == rb + 2 * p + 1 ? 1.0f : 0.0f));
    }
#pragma unroll
    for (int mm = 9; mm >= 1; mm--) {   // R <- I + (As*R)/mm
        unsigned long long o0 = __shfl_xor_sync(0xffffffffu, Rc2[0], 8, 16);
        unsigned long long o1 = __shfl_xor_sync(0xffffffffu, Rc2[1], 8, 16);
        unsigned long long L0 = hs ? o0 : Rc2[0], L1 = hs ? o1 : Rc2[1];
        unsigned long long H0 = hs ? Rc2[0] : o0, H1 = hs ? Rc2[1] : o1;
        float r0, r1, r2, r3, r4, r5, r6, r7;
        upk2(L0, r0, r1); upk2(L1, r2, r3);
        upk2(H0, r4, r5); upk2(H1, r6, r7);
        unsigned long long t0 = 0, t1 = 0, u;
        u = pk2(r0, r0); t0 = fma2_(A2[0][0], u, t0); t1 = fma2_(A2[0][1], u, t1);
        u = pk2(r1, r1); t0 = fma2_(A2[1][0], u, t0); t1 = fma2_(A2[1][1], u, t1);
        u = pk2(r2, r2); t0 = fma2_(A2[2][0], u, t0); t1 = fma2_(A2[2][1], u, t1);
        u = pk2(r3, r3); t0 = fma2_(A2[3][0], u, t0); t1 = fma2_(A2[3][1], u, t1);
        u = pk2(r4, r4); t0 = fma2_(A2[4][0], u, t0); t1 = fma2_(A2[4][1], u, t1);
        u = pk2(r5, r5); t0 = fma2_(A2[5][0], u, t0); t1 = fma2_(A2[5][1], u, t1);
        u = pk2(r6, r6); t0 = fma2_(A2[6][0], u, t0); t1 = fma2_(A2[6][1], u, t1);
        u = pk2(r7, r7); t0 = fma2_(A2[7][0], u, t0); t1 = fma2_(A2[7][1], u, t1);
        const float inv = 1.0f / (float)mm;
        const unsigned long long inv2 = pk2(inv, inv);
        Rc2[0] = fma2_(t0, inv2, idv2[0]);
        Rc2[1] = fma2_(t1, inv2, idv2[1]);
    }
#pragma unroll
    for (int sq = 0; sq < 2; sq++) {   // R <- R*R
        unsigned long long o0 = __shfl_xor_sync(0xffffffffu, Rc2[0], 8, 16);
        unsigned long long o1 = __shfl_xor_sync(0xffffffffu, Rc2[1], 8, 16);
        unsigned long long L0 = hs ? o0 : Rc2[0], L1 = hs ? o1 : Rc2[1];
        unsigned long long H0 = hs ? Rc2[0] : o0, H1 = hs ? Rc2[1] : o1;
        float r[8];
        upk2(L0, r[0], r[1]); upk2(L1, r[2], r[3]);
        upk2(H0, r[4], r[5]); upk2(H1, r[6], r[7]);
        unsigned long long t0 = 0, t1 = 0;
#pragma unroll
        for (int kk = 0; kk < 8; kk++) {
            unsigned long long a0 = __shfl_sync(0xffffffffu, Rc2[0], hs * 8 + kk, 16);
            unsigned long long a1 = __shfl_sync(0xffffffffu, Rc2[1], hs * 8 + kk, 16);
            unsigned long long u = pk2(r[kk], r[kk]);
            t0 = fma2_(a0, u, t0);
            t1 = fma2_(a1, u, t1);
        }
        Rc2[0] = t0; Rc2[1] = t1;
    }
    {
        float e0, e1, e2, e3;
        upk2(Rc2[0], e0, e1); upk2(Rc2[1], e2, e3);
        float* Em = &Esm[m * 72];
        Em[(rb + 0) * 8 + lc] = e0;
        Em[(rb + 1) * 8 + lc] = e1;
        Em[(rb + 2) * 8 + lc] = e2;
        Em[(rb + 3) * 8 + lc] = e3;
    }
    __syncthreads();

    // compact column-major copy for recurrence (2 bt * 512)
#pragma unroll
    for (int i = tid; i < 1024; i += 256) {
        int lbt = i >> 9, q = i & 511;
        int k = q >> 6, cq = (q >> 3) & 7, rq = q & 7;
        g_expT[(size_t)(bt0 + lbt) * 512 + q] = Esm[(lbt * 8 + k) * 72 + rq * 8 + cq];
    }
    // rho: fully coalesced streaming float4 (zeros + diagonal blocks)
#pragma unroll
    for (int i = tid; i < 2048; i += 256) {
        int lbt = i >> 10, rem = i & 1023, row = rem >> 4, q = rem & 15;
        int k = row >> 3;
        float4 v = make_float4(0.f, 0.f, 0.f, 0.f);
        if ((q >> 1) == k)
            v = *(const float4*)&Esm[(lbt * 8 + k) * 72 + (row & 7) * 8 + (q & 1) * 4];
        __stcs((float4*)rho + ((size_t)(bt0 + lbt) * 64 + row) * 16 + q, v);
    }
}

// ---------------- merged enc + phi kernel ----------------------------------
// blocks 0..255: encoder tiles; blocks 256..8415: phi/expm/rho tiles (2 bt).
__global__ void __launch_bounds__(256, 4)
k_encphi(const float* __restrict__ obs, const float* __restrict__ We,
         const float* __restrict__ be, float* __restrict__ latent,
         const float* __restrict__ act, const float* __restrict__ Wp,
         const float* __restrict__ bp, float* __restrict__ rho) {
    __shared__ __align__(16) EncPhiSmem sm;
    if (blockIdx.x < 256)
        enc_body(&sm, blockIdx.x, obs, We, be, latent);
    else
        phi_body(&sm, blockIdx.x - 256, act, Wp, bp, rho);
}

// ---------------- recurrence -----------------------------------------------
static __device__ __forceinline__ float stepf(float h, float4 e0, float4 e1) {
    float s0 = __shfl_sync(0xffffffffu, h, 0, 8) * e0.x;
    float s1 = __shfl_sync(0xffffffffu, h, 1, 8) * e0.y;
    s0 = fmaf(__shfl_sync(0xffffffffu, h, 2, 8), e0.z, s0);
    s1 = fmaf(__shfl_sync(0xffffffffu, h, 3, 8), e0.w, s1);
    s0 = fmaf(__shfl_sync(0xffffffffu, h, 4, 8), e1.x, s0);
    s1 = fmaf(__shfl_sync(0xffffffffu, h, 5, 8), e1.y, s1);
    s0 = fmaf(__shfl_sync(0xffffffffu, h, 6, 8), e1.z, s0);
    s1 = fmaf(__shfl_sync(0xffffffffu, h, 7, 8), e1.w, s1);
    return s0 + s1;
}

__global__ void __launch_bounds__(32) k_rec(const float* __restrict__ latent,
                                            float* __restrict__ pred) {
    const int lane = threadIdx.x;
    const int chain = blockIdx.x * 4 + (lane >> 3);  // 0..511
    const int b = chain >> 3, k = chain & 7, cc = lane & 7;
    const size_t pbase = (size_t)b * 256 * 64 + k * 8 + cc;
    float h = latent[pbase];
    pred[pbase] = h;
    const float4* base = (const float4*)g_expT + (size_t)b * 255 * 128 + k * 16 + cc * 2;

    float4 cur[16], nxt[16];
#pragma unroll
    for (int s = 0; s < 8; s++) {
        cur[2 * s] = base[(size_t)s * 128];
        cur[2 * s + 1] = base[(size_t)s * 128 + 1];
    }
    int t = 0;
    for (int gg = 1; gg < 32; gg++) {
#pragma unroll
        for (int s = 0; s < 8; s++) {
            int tt = gg * 8 + s;
            if (tt > 254) tt = 254;
            nxt[2 * s] = base[(size_t)tt * 128];
            nxt[2 * s + 1] = base[(size_t)tt * 128 + 1];
        }
#pragma unroll
        for (int s = 0; s < 8; s++) {
            h = stepf(h, cur[2 * s], cur[2 * s + 1]);
            pred[pbase + (size_t)(t + s + 1) * 64] = h;
        }
        t += 8;
#pragma unroll
        for (int i = 0; i < 16; i++) cur[i] = nxt[i];
    }
#pragma unroll
    for (int s = 0; s < 7; s++) {
        h = stepf(h, cur[2 * s], cur[2 * s + 1]);
        pred[pbase + (size_t)(249 + s) * 64] = h;
    }
}

// ---------------- decoder: pred_obs = pred_lat(16384x64) @ Wd(64x512) + bd --
// 128x128 tile, 256 thr, thread = 8 rows x 8 cols, K=64 loaded once.
__global__ void __launch_bounds__(256) k_dec(const float* __restrict__ lat,
                                             const float* __restrict__ Wd,
                                             const float* __restrict__ bd,
                                             float* __restrict__ out) {
    __shared__ __align__(16) float latS[128 * 68];
    __shared__ __align__(16) float Wsm[64 * 128];
    const int tid = threadIdx.x;
    const int tx = tid & 15, ty = tid >> 4;   // tx: col group (8 cols), ty: 0..15
    const int row0 = blockIdx.x * 128;
    const int col0 = blockIdx.y * 128;
    const int cb = col0 + tx * 8;

#pragma unroll
    for (int n = 0; n < 8; n++) {
        int i = tid + n * 256;
        int rr = i >> 4, c4 = (i & 15) * 4;
        *(float4*)&latS[rr * 68 + c4] =
            *(const float4*)&lat[(size_t)(row0 + rr) * 64 + c4];
    }
#pragma unroll
    for (int n = 0; n < 8; n++) {
        int i = tid + n * 256;
        int rk = i >> 5, c4 = (i & 31) * 4;
        int txc = c4 >> 3, q = (c4 >> 2) & 1;
        *(float4*)&Wsm[rk * 128 + q * 64 + txc * 4] =
            *(const float4*)&Wd[(size_t)rk * 512 + col0 + c4];
    }
    unsigned long long acc[8][4];
#pragma unroll
    for (int j = 0; j < 4; j++) {
        unsigned long long bv = pk2(bd[cb + 2 * j], bd[cb + 2 * j + 1]);
#pragma unroll
        for (int r = 0; r < 8; r++) acc[r][j] = bv;
    }
    __syncthreads();
#pragma unroll
    for (int k4 = 0; k4 < 16; k4++) {
        float4 o4[8];
#pragma unroll
        for (int r = 0; r < 8; r++)
            o4[r] = *(const float4*)&latS[(ty + r * 16) * 68 + k4 * 4];
#pragma unroll
        for (int kk = 0; kk < 4; kk++) {
            int k = k4 * 4 + kk;
            ulonglong2 w0 = *(const ulonglong2*)&Wsm[k * 128 + tx * 4];
            ulonglong2 w1 = *(const ulonglong2*)&Wsm[k * 128 + 64 + tx * 4];
#pragma unroll
            for (int r = 0; r < 8; r++) {
                float o = (kk == 0) ? o4[r].x : (kk == 1) ? o4[r].y
                          : (kk == 2) ? o4[r].z : o4[r].w;
                unsigned long long o2 = pk2(o, o);
                acc[r][0] = fma2_(o2, w0.x, acc[r][0]);
                acc[r][1] = fma2_(o2, w0.y, acc[r][1]);
                acc[r][2] = fma2_(o2, w1.x, acc[r][2]);
                acc[r][3] = fma2_(o2, w1.y, acc[r][3]);
            }
        }
    }
#pragma unroll
    for (int r = 0; r < 8; r++) {
        float v0, v1, v2, v3, v4, v5, v6, v7;
        upk2(acc[r][0], v0, v1); upk2(acc[r][1], v2, v3);
        upk2(acc[r][2], v4, v5); upk2(acc[r][3], v6, v7);
        float* dst = &out[(size_t)(row0 + ty + r * 16) * 512 + cb];
        __stcs((float4*)dst, make_float4(v0, v1, v2, v3));
        __stcs((float4*)(dst + 4), make_float4(v4, v5, v6, v7));
    }
}

extern "C" void kernel_launch(void* const* d_in, const int* in_sizes, int n_in,
                              void* d_out, int out_size) {
    const float* obs = (const float*)d_in[0];
    const float* act = (const float*)d_in[1];
    const float* We  = (const float*)d_in[2];
    const float* be  = (const float*)d_in[3];
    const float* Wd  = (const float*)d_in[4];
    const float* bd  = (const float*)d_in[5];
    const float* Wp  = (const float*)d_in[6];
    const float* bp  = (const float*)d_in[7];
    float* out = (float*)d_out;

    float* latent   = out;                 // [64,256,64]
    float* rho      = out + 1048576;       // [64,255,64,64]
    float* pred_lat = out + 67895296;      // [64,256,64]
    float* pred_obs = out + 68943872;      // [64,256,512]

    k_encphi<<<8416, 256>>>(obs, We, be, latent, act, Wp, bp, rho);
    k_rec<<<128, 32>>>(latent, pred_lat);
    k_dec<<<dim3(128, 4), 256>>>(pred_lat, Wd, bd, pred_obs);
}

// round 14
// speedup vs baseline: 1.0063x; 1.0063x over previous
#include <cuda_runtime.h>

#define NBT 16320  // 64 * 255

// compact exp blocks: g_expT[bt*512 + k*64 + c*8 + r] = E_k[r][c], bt = b*255+t
__device__ float g_expT[NBT * 512];

static __device__ __forceinline__ unsigned long long pk2(float lo, float hi) {
    unsigned long long r;
    asm("mov.b64 %0, {%1,%2};" : "=l"(r) : "f"(lo), "f"(hi));
    return r;
}
static __device__ __forceinline__ void upk2(unsigned long long v, float& lo, float& hi) {
    asm("mov.b64 {%0,%1}, %2;" : "=f"(lo), "=f"(hi) : "l"(v));
}
static __device__ __forceinline__ unsigned long long fma2_(unsigned long long a,
                                                           unsigned long long b,
                                                           unsigned long long c) {
    unsigned long long d;
    asm("fma.rn.f32x2 %0, %1, %2, %3;" : "=l"(d) : "l"(a), "l"(b), "l"(c));
    return d;
}

// ---------------- encoder: latent = obs(16384x512) @ We(512x64) + be -------
// 64x64 tile, 128 thr, thread = 8 rows x 4 cols. Register double-buffered K
// chunks of 64. W natural layout: cols tx*4 contiguous -> conflict-free.
__global__ void __launch_bounds__(128) k_enc(const float* __restrict__ obs,
                                             const float* __restrict__ We,
                                             const float* __restrict__ be,
                                             float* __restrict__ latent) {
    __shared__ __align__(16) float obsS[64 * 68];
    __shared__ __align__(16) float Wsm[64 * 64];
    const int tid = threadIdx.x;
    const int tx = tid & 15, ty = tid >> 4;   // tx: col group (4 cols), ty: 0..7
    const int row0 = blockIdx.x * 64;
    const int cb = tx * 4;

    unsigned long long acc[8][2];
    {
        unsigned long long b0 = pk2(be[cb + 0], be[cb + 1]);
        unsigned long long b1 = pk2(be[cb + 2], be[cb + 3]);
#pragma unroll
        for (int r = 0; r < 8; r++) { acc[r][0] = b0; acc[r][1] = b1; }
    }

    float4 rA[8], rW[8];
#pragma unroll
    for (int n = 0; n < 8; n++) {
        int i = tid + n * 128;
        int rr = i >> 4, c4 = (i & 15) * 4;
        rA[n] = *(const float4*)&obs[(size_t)(row0 + rr) * 512 + c4];
        rW[n] = *(const float4*)&We[(size_t)rr * 64 + c4];
    }
    for (int kc = 0; kc < 8; kc++) {
#pragma unroll
        for (int n = 0; n < 8; n++) {
            int i = tid + n * 128;
            int rr = i >> 4, c4 = (i & 15) * 4;
            *(float4*)&obsS[rr * 68 + c4] = rA[n];
            *(float4*)&Wsm[rr * 64 + c4] = rW[n];
        }
        __syncthreads();
        if (kc < 7) {
#pragma unroll
            for (int n = 0; n < 8; n++) {
                int i = tid + n * 128;
                int rr = i >> 4, c4 = (i & 15) * 4;
                rA[n] = *(const float4*)&obs[(size_t)(row0 + rr) * 512 + (kc + 1) * 64 + c4];
                rW[n] = *(const float4*)&We[(size_t)((kc + 1) * 64 + rr) * 64 + c4];
            }
        }
#pragma unroll
        for (int k4 = 0; k4 < 16; k4++) {
            float4 o4[8];
#pragma unroll
            for (int r = 0; r < 8; r++)
                o4[r] = *(const float4*)&obsS[(ty + r * 8) * 68 + k4 * 4];
#pragma unroll
            for (int kk = 0; kk < 4; kk++) {
                int k = k4 * 4 + kk;
                ulonglong2 w = *(const ulonglong2*)&Wsm[k * 64 + tx * 4];
#pragma unroll
                for (int r = 0; r < 8; r++) {
                    float o = (kk == 0) ? o4[r].x : (kk == 1) ? o4[r].y
                              : (kk == 2) ? o4[r].z : o4[r].w;
                    unsigned long long o2 = pk2(o, o);
                    acc[r][0] = fma2_(o2, w.x, acc[r][0]);
                    acc[r][1] = fma2_(o2, w.y, acc[r][1]);
                }
            }
        }
        __syncthreads();
    }
#pragma unroll
    for (int r = 0; r < 8; r++) {
        float v0, v1, v2, v3;
        upk2(acc[r][0], v0, v1); upk2(acc[r][1], v2, v3);
        *(float4*)&latent[(size_t)(row0 + ty + r * 8) * 64 + cb] =
            make_float4(v0, v1, v2, v3);
    }
}

// ---------------- phi: GEMM + expm + rho, 8 bt per block -------------------
// W_phi read once per 8 bt (half of R9 traffic). GEMM: in-loop LDG.64, 8
// f32x2 accumulators. expm: 16 lanes/matrix (32-reg A), 4 sequential rounds.
__global__ void __launch_bounds__(256) k_phi(const float* __restrict__ act,
                                             const float* __restrict__ Wp,
                                             const float* __restrict__ bp,
                                             float* __restrict__ rho) {
    __shared__ __align__(16) float actS[8][32];
    __shared__ __align__(16) float Ablk[64 * 68];  // 64 A blocks [m][r*8+c]
    __shared__ __align__(16) float Esm[64 * 72];   // 64 exp blocks
    const int tid = threadIdx.x;
    const int bt0 = blockIdx.x * 8;

    for (int i = tid; i < 256; i += 256)
        actS[i >> 5][i & 31] = act[(size_t)bt0 * 32 + i];
    __syncthreads();

    // after_phi = act @ Wp + bp for 8 bt's
    {
        const int j0 = tid * 2;
        const unsigned long long bb2 = *(const unsigned long long*)&bp[j0];
        unsigned long long s[8];
#pragma unroll
        for (int lbt = 0; lbt < 8; lbt++) s[lbt] = bb2;
#pragma unroll 8
        for (int a = 0; a < 32; a++) {
            unsigned long long w = *(const unsigned long long*)&Wp[a * 512 + j0];
#pragma unroll
            for (int lbt = 0; lbt < 8; lbt++) {
                float f = actS[lbt][a];
                s[lbt] = fma2_(pk2(f, f), w, s[lbt]);
            }
        }
        const int k = j0 >> 6, rowj = (j0 >> 3) & 7, colj = j0 & 7;
#pragma unroll
        for (int lbt = 0; lbt < 8; lbt++) {
            float v0, v1;
            upk2(s[lbt], v0, v1);
            // blocks.transpose(0,2,1): A[colj][rowj] = after_phi[j]
            Ablk[(lbt * 8 + k) * 68 + colj * 8 + rowj] = v0;
            Ablk[(lbt * 8 + k) * 68 + (colj + 1) * 8 + rowj] = v1;
        }
    }
    __syncthreads();

    // expm: 16 lanes per matrix; lane l = tid&15: lc = l&7 (column),
    // hs = l>>3 (row half, 4 rows). exp(A) = (Taylor10(A/4))^4.
    const int l = tid & 15, lc = l & 7, hs = l >> 3;
    const int rb = hs * 4;
#pragma unroll 1
    for (int rd = 0; rd < 4; rd++) {
        const int m = rd * 16 + (tid >> 4);
        const float* Am = &Ablk[m * 68];

        // A2[kk][p] = ( As[rb+2p][kk], As[rb+2p+1][kk] ), As = A*0.25
        unsigned long long A2[8][2];
#pragma unroll
        for (int p = 0; p < 2; p++) {
            float4 a0 = *(const float4*)&Am[(rb + 2 * p) * 8];
            float4 a1 = *(const float4*)&Am[(rb + 2 * p) * 8 + 4];
            float4 b0 = *(const float4*)&Am[(rb + 2 * p + 1) * 8];
            float4 b1 = *(const float4*)&Am[(rb + 2 * p + 1) * 8 + 4];
            A2[0][p] = pk2(a0.x * 0.25f, b0.x * 0.25f);
            A2[1][p] = pk2(a0.y * 0.25f, b0.y * 0.25f);
            A2[2][p] = pk2(a0.z * 0.25f, b0.z * 0.25f);
            A2[3][p] = pk2(a0.w * 0.25f, b0.w * 0.25f);
            A2[4][p] = pk2(a1.x * 0.25f, b1.x * 0.25f);
            A2[5][p] = pk2(a1.y * 0.25f, b1.y * 0.25f);
            A2[6][p] = pk2(a1.z * 0.25f, b1.z * 0.25f);
            A2[7][p] = pk2(a1.w * 0.25f, b1.w * 0.25f);
        }
        unsigned long long idv2[2];
#pragma unroll
        for (int p = 0; p < 2; p++)
            idv2[p] = pk2(lc == rb + 2 * p ? 1.0f : 0.0f,
                          lc == rb + 2 * p + 1 ? 1.0f : 0.0f);
        unsigned long long Rc2[2];
#pragma unroll
        for (int p = 0; p < 2; p++) {
            float a0 = Am[(rb + 2 * p) * 8 + lc] * 0.025f;
            float a1 = Am[(rb + 2 * p + 1) * 8 + lc] * 0.025f;
            Rc2[p] = pk2(a0 + (lc == rb + 2 * p ? 1.0f : 0.0f),
                         a1 + (lc == rb + 2 * p + 1 ? 1.0f : 0.0f));
        }
#pragma unroll
        for (int mm = 9; mm >= 1; mm--) {   // R <- I + (As*R)/mm
            unsigned long long o0 = __shfl_xor_sync(0xffffffffu, Rc2[0], 8, 16);
            unsigned long long o1 = __shfl_xor_sync(0xffffffffu, Rc2[1], 8, 16);
            unsigned long long L0 = hs ? o0 : Rc2[0], L1 = hs ? o1 : Rc2[1];
            unsigned long long H0 = hs ? Rc2[0] : o0, H1 = hs ? Rc2[1] : o1;
            float r0, r1, r2, r3, r4, r5, r6, r7;
            upk2(L0, r0, r1); upk2(L1, r2, r3);
            upk2(H0, r4, r5); upk2(H1, r6, r7);
            unsigned long long t0 = 0, t1 = 0, u;
            u = pk2(r0, r0); t0 = fma2_(A2[0][0], u, t0); t1 = fma2_(A2[0][1], u, t1);
            u = pk2(r1, r1); t0 = fma2_(A2[1][0], u, t0); t1 = fma2_(A2[1][1], u, t1);
            u = pk2(r2, r2); t0 = fma2_(A2[2][0], u, t0); t1 = fma2_(A2[2][1], u, t1);
            u = pk2(r3, r3); t0 = fma2_(A2[3][0], u, t0); t1 = fma2_(A2[3][1], u, t1);
            u = pk2(r4, r4); t0 = fma2_(A2[4][0], u, t0); t1 = fma2_(A2[4][1], u, t1);
            u = pk2(r5, r5); t0 = fma2_(A2[5][0], u, t0); t1 = fma2_(A2[5][1], u, t1);
            u = pk2(r6, r6); t0 = fma2_(A2[6][0], u, t0); t1 = fma2_(A2[6][1], u, t1);
            u = pk2(r7, r7); t0 = fma2_(A2[7][0], u, t0); t1 = fma2_(A2[7][1], u, t1);
            const float inv = 1.0f / (float)mm;
            const unsigned long long inv2 = pk2(inv, inv);
            Rc2[0] = fma2_(t0, inv2, idv2[0]);
            Rc2[1] = fma2_(t1, inv2, idv2[1]);
        }
#pragma unroll
        for (int sq = 0; sq < 2; sq++) {   // R <- R*R
            unsigned long long o0 = __shfl_xor_sync(0xffffffffu, Rc2[0], 8, 16);
            unsigned long long o1 = __shfl_xor_sync(0xffffffffu, Rc2[1], 8, 16);
            unsigned long long L0 = hs ? o0 : Rc2[0], L1 = hs ? o1 : Rc2[1];
            unsigned long long H0 = hs ? Rc2[0] : o0, H1 = hs ? Rc2[1] : o1;
            float r[8];
            upk2(L0, r[0], r[1]); upk2(L1, r[2], r[3]);
            upk2(H0, r[4], r[5]); upk2(H1, r[6], r[7]);
            unsigned long long t0 = 0, t1 = 0;
#pragma unroll
            for (int kk = 0; kk < 8; kk++) {
                unsigned long long a0 = __shfl_sync(0xffffffffu, Rc2[0], hs * 8 + kk, 16);
                unsigned long long a1 = __shfl_sync(0xffffffffu, Rc2[1], hs * 8 + kk, 16);
                unsigned long long u = pk2(r[kk], r[kk]);
                t0 = fma2_(a0, u, t0);
                t1 = fma2_(a1, u, t1);
            }
            Rc2[0] = t0; Rc2[1] = t1;
        }
        {
            float e0, e1, e2, e3;
            upk2(Rc2[0], e0, e1); upk2(Rc2[1], e2, e3);
            float* Em = &Esm[m * 72];
            Em[(rb + 0) * 8 + lc] = e0;
            Em[(rb + 1) * 8 + lc] = e1;
            Em[(rb + 2) * 8 + lc] = e2;
            Em[(rb + 3) * 8 + lc] = e3;
        }
    }
    __syncthreads();

    // compact column-major copy for recurrence (8 bt * 512)
#pragma unroll
    for (int i = tid; i < 4096; i += 256) {
        int lbt = i >> 9, q = i & 511;
        int k = q >> 6, cq = (q >> 3) & 7, rq = q & 7;
        g_expT[(size_t)(bt0 + lbt) * 512 + q] = Esm[(lbt * 8 + k) * 72 + rq * 8 + cq];
    }
    // rho: fully coalesced streaming float4 (zeros + diagonal blocks)
#pragma unroll
    for (int i = tid; i < 8192; i += 256) {
        int lbt = i >> 10, rem = i & 1023, row = rem >> 4, q = rem & 15;
        int k = row >> 3;
        float4 v = make_float4(0.f, 0.f, 0.f, 0.f);
        if ((q >> 1) == k)
            v = *(const float4*)&Esm[(lbt * 8 + k) * 72 + (row & 7) * 8 + (q & 1) * 4];
        __stcs((float4*)rho + ((size_t)(bt0 + lbt) * 64 + row) * 16 + q, v);
    }
}

// ---------------- recurrence -----------------------------------------------
static __device__ __forceinline__ float stepf(float h, float4 e0, float4 e1) {
    float s0 = __shfl_sync(0xffffffffu, h, 0, 8) * e0.x;
    float s1 = __shfl_sync(0xffffffffu, h, 1, 8) * e0.y;
    s0 = fmaf(__shfl_sync(0xffffffffu, h, 2, 8), e0.z, s0);
    s1 = fmaf(__shfl_sync(0xffffffffu, h, 3, 8), e0.w, s1);
    s0 = fmaf(__shfl_sync(0xffffffffu, h, 4, 8), e1.x, s0);
    s1 = fmaf(__shfl_sync(0xffffffffu, h, 5, 8), e1.y, s1);
    s0 = fmaf(__shfl_sync(0xffffffffu, h, 6, 8), e1.z, s0);
    s1 = fmaf(__shfl_sync(0xffffffffu, h, 7, 8), e1.w, s1);
    return s0 + s1;
}

__global__ void __launch_bounds__(32) k_rec(const float* __restrict__ latent,
                                            float* __restrict__ pred) {
    const int lane = threadIdx.x;
    const int chain = blockIdx.x * 4 + (lane >> 3);  // 0..511
    const int b = chain >> 3, k = chain & 7, cc = lane & 7;
    const size_t pbase = (size_t)b * 256 * 64 + k * 8 + cc;
    float h = latent[pbase];
    pred[pbase] = h;
    const float4* base = (const float4*)g_expT + (size_t)b * 255 * 128 + k * 16 + cc * 2;

    float4 cur[16], nxt[16];
#pragma unroll
    for (int s = 0; s < 8; s++) {
        cur[2 * s] = base[(size_t)s * 128];
        cur[2 * s + 1] = base[(size_t)s * 128 + 1];
    }
    int t = 0;
    for (int gg = 1; gg < 32; gg++) {
#pragma unroll
        for (int s = 0; s < 8; s++) {
            int tt = gg * 8 + s;
            if (tt > 254) tt = 254;
            nxt[2 * s] = base[(size_t)tt * 128];
            nxt[2 * s + 1] = base[(size_t)tt * 128 + 1];
        }
#pragma unroll
        for (int s = 0; s < 8; s++) {
            h = stepf(h, cur[2 * s], cur[2 * s + 1]);
            pred[pbase + (size_t)(t + s + 1) * 64] = h;
        }
        t += 8;
#pragma unroll
        for (int i = 0; i < 16; i++) cur[i] = nxt[i];
    }
#pragma unroll
    for (int s = 0; s < 7; s++) {
        h = stepf(h, cur[2 * s], cur[2 * s + 1]);
        pred[pbase + (size_t)(249 + s) * 64] = h;
    }
}

// ---------------- decoder: pred_obs = pred_lat(16384x64) @ Wd(64x512) + bd --
// 128x128 tile, 256 thr, thread = 8 rows x 8 cols, K=64 loaded once.
__global__ void __launch_bounds__(256) k_dec(const float* __restrict__ lat,
                                             const float* __restrict__ Wd,
                                             const float* __restrict__ bd,
                                             float* __restrict__ out) {
    __shared__ __align__(16) float latS[128 * 68];
    __shared__ __align__(16) float Wsm[64 * 128];
    const int tid = threadIdx.x;
    const int tx = tid & 15, ty = tid >> 4;   // tx: col group (8 cols), ty: 0..15
    const int row0 = blockIdx.x * 128;
    const int col0 = blockIdx.y * 128;
    const int cb = col0 + tx * 8;

#pragma unroll
    for (int n = 0; n < 8; n++) {
        int i = tid + n * 256;
        int rr = i >> 4, c4 = (i & 15) * 4;
        *(float4*)&latS[rr * 68 + c4] =
            *(const float4*)&lat[(size_t)(row0 + rr) * 64 + c4];
    }
#pragma unroll
    for (int n = 0; n < 8; n++) {
        int i = tid + n * 256;
        int rk = i >> 5, c4 = (i & 31) * 4;
        int txc = c4 >> 3, q = (c4 >> 2) & 1;
        *(float4*)&Wsm[rk * 128 + q * 64 + txc * 4] =
            *(const float4*)&Wd[(size_t)rk * 512 + col0 + c4];
    }
    unsigned long long acc[8][4];
#pragma unroll
    for (int j = 0; j < 4; j++) {
        unsigned long long bv = pk2(bd[cb + 2 * j], bd[cb + 2 * j + 1]);
#pragma unroll
        for (int r = 0; r < 8; r++) acc[r][j] = bv;
    }
    __syncthreads();
#pragma unroll
    for (int k4 = 0; k4 < 16; k4++) {
        float4 o4[8];
#pragma unroll
        for (int r = 0; r < 8; r++)
            o4[r] = *(const float4*)&latS[(ty + r * 16) * 68 + k4 * 4];
#pragma unroll
        for (int kk = 0; kk < 4; kk++) {
            int k = k4 * 4 + kk;
            ulonglong2 w0 = *(const ulonglong2*)&Wsm[k * 128 + tx * 4];
            ulonglong2 w1 = *(const ulonglong2*)&Wsm[k * 128 + 64 + tx * 4];
#pragma unroll
            for (int r = 0; r < 8; r++) {
                float o = (kk == 0) ? o4[r].x : (kk == 1) ? o4[r].y
                          : (kk == 2) ? o4[r].z : o4[r].w;
                unsigned long long o2 = pk2(o, o);
                acc[r][0] = fma2_(o2, w0.x, acc[r][0]);
                acc[r][1] = fma2_(o2, w0.y, acc[r][1]);
                acc[r][2] = fma2_(o2, w1.x, acc[r][2]);
                acc[r][3] = fma2_(o2, w1.y, acc[r][3]);
            }
        }
    }
#pragma unroll
    for (int r = 0; r < 8; r++) {
        float v0, v1, v2, v3, v4, v5, v6, v7;
        upk2(acc[r][0], v0, v1); upk2(acc[r][1], v2, v3);
        upk2(acc[r][2], v4, v5); upk2(acc[r][3], v6, v7);
        float* dst = &out[(size_t)(row0 + ty + r * 16) * 512 + cb];
        __stcs((float4*)dst, make_float4(v0, v1, v2, v3));
        __stcs((float4*)(dst + 4), make_float4(v4, v5, v6, v7));
    }
}

extern "C" void kernel_launch(void* const* d_in, const int* in_sizes, int n_in,
                              void* d_out, int out_size) {
    const float* obs = (const float*)d_in[0];
    const float* act = (const float*)d_in[1];
    const float* We  = (const float*)d_in[2];
    const float* be  = (const float*)d_in[3];
    const float* Wd  = (const float*)d_in[4];
    const float* bd  = (const float*)d_in[5];
    const float* Wp  = (const float*)d_in[6];
    const float* bp  = (const float*)d_in[7];
    float* out = (float*)d_out;

    float* latent   = out;                 // [64,256,64]
    float* rho      = out + 1048576;       // [64,255,64,64]
    float* pred_lat = out + 67895296;      // [64,256,64]
    float* pred_obs = out + 68943872;      // [64,256,512]

    k_phi<<<2040, 256>>>(act, Wp, bp, rho);
    k_enc<<<256, 128>>>(obs, We, be, latent);
    k_rec<<<128, 32>>>(latent, pred_lat);
    k_dec<<<dim3(128, 4), 256>>>(pred_lat, Wd, bd, pred_obs);
}